// round 15
// baseline (speedup 1.0000x reference)
#include <cuda_runtime.h>
#include <cuda_bf16.h>
#include <cstdint>
#include <math.h>

#define T_STEPS 512
#define NBATCH  256
#define HID     256

// 134 MB scratch for the precomputed input projection xp[t][b][h]
__device__ float g_xp[T_STEPS * NBATCH * HID];

// ---------------------------------------------------------------------------
// helpers
// ---------------------------------------------------------------------------
__device__ __forceinline__ uint32_t smem_u32(const void* p) {
    uint32_t a;
    asm("{ .reg .u64 t; cvta.to.shared.u64 t, %1; cvt.u32.u64 %0, t; }"
        : "=r"(a) : "l"(p));
    return a;
}
__device__ __forceinline__ void fma2(unsigned long long& d,
                                     unsigned long long a,
                                     unsigned long long b) {
    asm("fma.rn.f32x2 %0, %1, %2, %0;" : "+l"(d) : "l"(a), "l"(b));
}
__device__ __forceinline__ float hsum2(unsigned long long v) {
    return __uint_as_float((unsigned)v) + __uint_as_float((unsigned)(v >> 32));
}
__device__ __forceinline__ float fast_tanh(float z) {
    float e = __expf(2.0f * z);
    return 1.0f - __fdividef(2.0f, e + 1.0f);
}
// pack two f32 -> bf16x2 (first arg -> low half = lower k index)
__device__ __forceinline__ uint32_t pack_bf16x2(float lo, float hi) {
    uint32_t r;
    asm("cvt.rn.bf16x2.f32 %0, %1, %2;" : "=r"(r) : "f"(hi), "f"(lo));
    return r;
}
__device__ __forceinline__ void mbar_wait_cluster(uint32_t mbar, uint32_t parity) {
    uint32_t done;
    asm volatile(
        "{ .reg .pred p;\n"
        "  mbarrier.try_wait.parity.acquire.cluster.shared::cta.b64 p, [%1], %2;\n"
        "  selp.b32 %0, 1, 0, p; }"
        : "=r"(done) : "r"(mbar), "r"(parity) : "memory");
    if (!done) {
        asm volatile(
            "{ .reg .pred P;\n"
            "LW%=:\n"
            "  mbarrier.try_wait.parity.acquire.cluster.shared::cta.b64 P, [%0], %1, 0x989680;\n"
            "  @P bra.uni LD%=;\n"
            "  bra.uni LW%=;\n"
            "LD%=: }"
            :: "r"(mbar), "r"(parity) : "memory");
    }
}

// ldmatrix x4 (16B-aligned per-lane addresses)
#define LDSM4(R, addr) \
    asm volatile("ldmatrix.sync.aligned.m8n8.x4.shared.b16 {%0,%1,%2,%3}, [%4];" \
        : "=r"((R)[0]), "=r"((R)[1]), "=r"((R)[2]), "=r"((R)[3]) : "r"(addr))

// D += A * B (bf16 -> f32)
__device__ __forceinline__ void mma_bf16(float* d, const uint32_t* a,
                                         uint32_t b0, uint32_t b1) {
    asm volatile(
        "mma.sync.aligned.m16n8k16.row.col.f32.bf16.bf16.f32 "
        "{%0,%1,%2,%3}, {%4,%5,%6,%7}, {%8,%9}, {%0,%1,%2,%3};"
        : "+f"(d[0]), "+f"(d[1]), "+f"(d[2]), "+f"(d[3])
        : "r"(a[0]), "r"(a[1]), "r"(a[2]), "r"(a[3]), "r"(b0), "r"(b1));
}

// split float4 into bf16 hi + bf16 residual-lo, store 8B each
__device__ __forceinline__ void cvt_store_split(char* hi_base, char* lo_base,
                                                float4 v, uint32_t off) {
    uint32_t h01 = pack_bf16x2(v.x, v.y), h23 = pack_bf16x2(v.z, v.w);
    float f0 = __uint_as_float(h01 << 16);
    float f1 = __uint_as_float(h01 & 0xffff0000u);
    float f2 = __uint_as_float(h23 << 16);
    float f3 = __uint_as_float(h23 & 0xffff0000u);
    uint32_t l01 = pack_bf16x2(v.x - f0, v.y - f1);
    uint32_t l23 = pack_bf16x2(v.z - f2, v.w - f3);
    *(uint2*)(hi_base + off) = make_uint2(h01, h23);
    *(uint2*)(lo_base + off) = make_uint2(l01, l23);
}

// ---------------------------------------------------------------------------
// Kernel 1: xp = x @ W_ih^T + (b_ih+b_hh) via mma.sync bf16x3 split.
// PROVEN R12 version (313 us) — byte-identical, do not touch.
// ---------------------------------------------------------------------------
#define APAD 40

__global__ void __launch_bounds__(256) input_proj_mma(
    const float* __restrict__ x, const float* __restrict__ W_ih,
    const float* __restrict__ b_ih, const float* __restrict__ b_hh)
{
    __shared__ __align__(16) __nv_bfloat16 sAhi[128 * APAD];
    __shared__ __align__(16) __nv_bfloat16 sAlo[128 * APAD];
    __shared__ __align__(16) __nv_bfloat16 sBhi[128 * APAD];
    __shared__ __align__(16) __nv_bfloat16 sBlo[128 * APAD];
    __shared__ float s_bias[128];

    const int tid = threadIdx.x, lane = tid & 31, wid = tid >> 5;
    const int wm = wid & 3, wn = wid >> 2;          // 4 m-warps x 2 n-warps
    const int m0 = blockIdx.x * 128, n0 = blockIdx.y * 128;

    if (tid < 128) s_bias[tid] = b_ih[n0 + tid] + b_hh[n0 + tid];

    float acc[2][8][4];
    #pragma unroll
    for (int i = 0; i < 2; i++)
        #pragma unroll
        for (int j = 0; j < 8; j++)
            #pragma unroll
            for (int q = 0; q < 4; q++) acc[i][j][q] = 0.0f;

    const int lr = lane & 15, lc = (lane >> 4) << 3;
    uint32_t offA[2][2], offB[4][2];
    #pragma unroll
    for (int mf = 0; mf < 2; mf++)
        #pragma unroll
        for (int kf = 0; kf < 2; kf++)
            offA[mf][kf] = (uint32_t)(((wm * 32 + mf * 16 + lr) * APAD + kf * 16 + lc) * 2);
    #pragma unroll
    for (int n2 = 0; n2 < 4; n2++)
        #pragma unroll
        for (int kf = 0; kf < 2; kf++)
            offB[n2][kf] = (uint32_t)(((wn * 64 + n2 * 16 + lr) * APAD + kf * 16 + lc) * 2);

    const uint32_t aHi = smem_u32(sAhi), aLo = smem_u32(sAlo);
    const uint32_t bHi = smem_u32(sBhi), bLo = smem_u32(sBlo);

    const float4* xg = (const float4*)x;      // 75 float4 per row (K=300)
    const float4* wg = (const float4*)W_ih;

    for (int kc = 0; kc < 10; kc++) {         // K padded 300 -> 320
        #pragma unroll
        for (int l = 0; l < 4; l++) {         // A: 128 rows x 8 float4
            int idx = l * 256 + tid, r = idx >> 3, c4 = idx & 7, g4 = kc * 8 + c4;
            float4 v = make_float4(0.f, 0.f, 0.f, 0.f);
            if (g4 < 75) v = xg[(size_t)(m0 + r) * 75 + g4];
            cvt_store_split((char*)sAhi, (char*)sAlo, v, (uint32_t)(r * 80 + c4 * 8));
        }
        #pragma unroll
        for (int l = 0; l < 4; l++) {         // B: 128 W rows x 8 float4
            int idx = l * 256 + tid, r = idx >> 3, c4 = idx & 7, g4 = kc * 8 + c4;
            float4 v = make_float4(0.f, 0.f, 0.f, 0.f);
            if (g4 < 75) v = wg[(size_t)(n0 + r) * 75 + g4];
            cvt_store_split((char*)sBhi, (char*)sBlo, v, (uint32_t)(r * 80 + c4 * 8));
        }
        __syncthreads();

        uint32_t Ah[2][2][4], Al[2][2][4], Bf[4][2][4];
        #pragma unroll
        for (int mf = 0; mf < 2; mf++)
            #pragma unroll
            for (int kf = 0; kf < 2; kf++) {
                LDSM4(Ah[mf][kf], aHi + offA[mf][kf]);
                LDSM4(Al[mf][kf], aLo + offA[mf][kf]);
            }
        #pragma unroll
        for (int n2 = 0; n2 < 4; n2++)
            #pragma unroll
            for (int kf = 0; kf < 2; kf++)
                LDSM4(Bf[n2][kf], bHi + offB[n2][kf]);

        // hi*hi + lo*hi
        #pragma unroll
        for (int mf = 0; mf < 2; mf++)
            #pragma unroll
            for (int n2 = 0; n2 < 4; n2++)
                #pragma unroll
                for (int kf = 0; kf < 2; kf++) {
                    mma_bf16(acc[mf][n2 * 2 + 0], Ah[mf][kf], Bf[n2][kf][0], Bf[n2][kf][2]);
                    mma_bf16(acc[mf][n2 * 2 + 1], Ah[mf][kf], Bf[n2][kf][1], Bf[n2][kf][3]);
                    mma_bf16(acc[mf][n2 * 2 + 0], Al[mf][kf], Bf[n2][kf][0], Bf[n2][kf][2]);
                    mma_bf16(acc[mf][n2 * 2 + 1], Al[mf][kf], Bf[n2][kf][1], Bf[n2][kf][3]);
                }
        // hi*lo
        #pragma unroll
        for (int n2 = 0; n2 < 4; n2++)
            #pragma unroll
            for (int kf = 0; kf < 2; kf++)
                LDSM4(Bf[n2][kf], bLo + offB[n2][kf]);
        #pragma unroll
        for (int mf = 0; mf < 2; mf++)
            #pragma unroll
            for (int n2 = 0; n2 < 4; n2++)
                #pragma unroll
                for (int kf = 0; kf < 2; kf++) {
                    mma_bf16(acc[mf][n2 * 2 + 0], Ah[mf][kf], Bf[n2][kf][0], Bf[n2][kf][2]);
                    mma_bf16(acc[mf][n2 * 2 + 1], Ah[mf][kf], Bf[n2][kf][1], Bf[n2][kf][3]);
                }
        __syncthreads();
    }

    #pragma unroll
    for (int mf = 0; mf < 2; mf++)
        #pragma unroll
        for (int nf = 0; nf < 8; nf++) {
            int row = m0 + wm * 32 + mf * 16 + (lane >> 2);
            int colL = wn * 64 + nf * 8 + (lane & 3) * 2;
            float2 v;
            v.x = acc[mf][nf][0] + s_bias[colL];
            v.y = acc[mf][nf][1] + s_bias[colL + 1];
            *(float2*)&g_xp[(size_t)row * HID + n0 + colL] = v;
            v.x = acc[mf][nf][2] + s_bias[colL];
            v.y = acc[mf][nf][3] + s_bias[colL + 1];
            *(float2*)&g_xp[(size_t)(row + 8) * HID + n0 + colL] = v;
        }
}

// ---------------------------------------------------------------------------
// Kernel 2: persistent recurrence, phase-split with TWO ping-pong mbarriers.
// 64 clusters x 2 CTAs, 4 batch / cluster, 512 threads (16 warps):
// thread = (row ha 0..127, k-quarter kq 0..3); W slice 64 floats in regs.
// Protocol (deadlock-free, R13 post-mortem):
//   publish@t  : kq0 DSMEM-stores h[t+1] peer half, release-arrive on
//                peer mbar[(t+1)&1] (count=128).
//   wait@t     : peer-half quarters wait own mbar[t&1], parity (t>>1)&1,
//                consuming publish@(t-1) (bootstrap completes mbar[0] ph0).
//   Two barriers => parity aliasing needs 4 steps of skew; the sync/wait
//   chain bounds skew at <2 steps. Final wait (t=512: mbar[0], parity 0)
//   by ALL threads covers publish@511 before the tail reads h[512]; final
//   cluster barrier before exit.
// ---------------------------------------------------------------------------
__global__ void __cluster_dims__(2, 1, 1) __launch_bounds__(512, 1)
rnn_scan_kernel(const float* __restrict__ W_hh, const float* __restrict__ W_fc,
                const float* __restrict__ b_fc, float* __restrict__ out)
{
    __shared__ __align__(16) float hs[2 * 4 * HID];   // ping-pong h, 4 batches
    __shared__ float red[2][3 * 4 * 128];             // kq1..3 partials, x2 parity
    __shared__ __align__(8) unsigned long long mb[2];

    const int tid = threadIdx.x;
    uint32_t rank;
    asm("mov.u32 %0, %%cluster_ctarank;" : "=r"(rank));
    const int bbase = (blockIdx.x >> 1) * 4;
    const int ha = tid & 127, kq = tid >> 7;          // kq warp-uniform
    const int grow = (int)rank * 128 + ha;            // global h row
    const bool own = ((kq >> 1) == (int)rank);        // k-quarter in own half?

    // W_hh[grow][kq*64 .. +64) -> 32 packed-f32x2 registers
    unsigned long long w[32];
    {
        const unsigned long long* Wr =
            (const unsigned long long*)(W_hh + (size_t)grow * HID + kq * 64);
        #pragma unroll
        for (int j = 0; j < 32; j++) w[j] = Wr[j];
    }
    for (int i = tid; i < 2 * 4 * HID; i += 512) hs[i] = 0.0f;
    const uint32_t mbar0 = smem_u32(&mb[0]);
    if (tid == 0) {
        asm volatile("mbarrier.init.shared.b64 [%0], %1;" :: "r"(mbar0),     "r"(128) : "memory");
        asm volatile("mbarrier.init.shared.b64 [%0], %1;" :: "r"(mbar0 + 8), "r"(128) : "memory");
    }
    __syncthreads();
    // peer mbar init + hs zero visible before any DSMEM traffic / arrives
    asm volatile("barrier.cluster.arrive.aligned;" ::: "memory");
    asm volatile("barrier.cluster.wait.aligned;" ::: "memory");

    uint32_t peer_mbar0, peer_hs;
    asm("mapa.shared::cluster.u32 %0, %1, %2;" : "=r"(peer_mbar0) : "r"(mbar0), "r"(1u - rank));
    asm("mapa.shared::cluster.u32 %0, %1, %2;" : "=r"(peer_hs) : "r"(smem_u32(hs)), "r"(1u - rank));

    // bootstrap: h[0]=0 valid on both sides; complete mbar[0] phase 0 so the
    // step-0 peer-half wait passes immediately.
    if (kq == 0)
        asm volatile("mbarrier.arrive.release.cluster.shared::cluster.b64 _, [%0];"
                     :: "r"(peer_mbar0) : "memory");

    const float* xp = g_xp + (size_t)bbase * HID + grow;

    for (int t = 0; t < T_STEPS; t++) {
        const int p = t & 1;
        float xv0 = 0.f, xv1 = 0.f, xv2 = 0.f, xv3 = 0.f;
        if (kq == 0) {                        // issue LDGs before any wait
            xv0 = __ldg(xp);
            xv1 = __ldg(xp + HID);
            xv2 = __ldg(xp + 2 * HID);
            xv3 = __ldg(xp + 3 * HID);
        }
        xp += (size_t)NBATCH * HID;

        // peer half of h[t]: mbar[t&1], parity (t>>1)&1
        if (!own) mbar_wait_cluster(mbar0 + (uint32_t)((t & 1) * 8),
                                    (uint32_t)((t >> 1) & 1));

        const float* rb = hs + p * 1024 + kq * 64;
        const ulonglong2* h0p = (const ulonglong2*)(rb);
        const ulonglong2* h1p = (const ulonglong2*)(rb + HID);
        const ulonglong2* h2p = (const ulonglong2*)(rb + 2 * HID);
        const ulonglong2* h3p = (const ulonglong2*)(rb + 3 * HID);

        unsigned long long a0x = 0, a0y = 0, a1x = 0, a1y = 0;
        unsigned long long a2x = 0, a2y = 0, a3x = 0, a3y = 0;
        #pragma unroll
        for (int jj = 0; jj < 16; jj++) {     // 4 k per iter, broadcast LDS
            ulonglong2 h0 = h0p[jj], h1 = h1p[jj], h2 = h2p[jj], h3 = h3p[jj];
            fma2(a0x, w[2 * jj], h0.x); fma2(a0y, w[2 * jj + 1], h0.y);
            fma2(a1x, w[2 * jj], h1.x); fma2(a1y, w[2 * jj + 1], h1.y);
            fma2(a2x, w[2 * jj], h2.x); fma2(a2y, w[2 * jj + 1], h2.y);
            fma2(a3x, w[2 * jj], h3.x); fma2(a3y, w[2 * jj + 1], h3.y);
        }
        float s0 = hsum2(a0x) + hsum2(a0y);
        float s1 = hsum2(a1x) + hsum2(a1y);
        float s2 = hsum2(a2x) + hsum2(a2y);
        float s3 = hsum2(a3x) + hsum2(a3y);

        if (kq != 0) {
            float* rd = red[p] + (kq - 1) * 512;
            rd[0 * 128 + ha] = s0; rd[1 * 128 + ha] = s1;
            rd[2 * 128 + ha] = s2; rd[3 * 128 + ha] = s3;
        }
        __syncthreads();                      // partials ready
        if (kq == 0) {
            const float* rd = red[p];
            float v0 = fast_tanh(s0 + rd[0 + ha] + rd[512 + ha] + rd[1024 + ha] + xv0);
            float v1 = fast_tanh(s1 + rd[128 + ha] + rd[640 + ha] + rd[1152 + ha] + xv1);
            float v2 = fast_tanh(s2 + rd[256 + ha] + rd[768 + ha] + rd[1280 + ha] + xv2);
            float v3 = fast_tanh(s3 + rd[384 + ha] + rd[896 + ha] + rd[1408 + ha] + xv3);
            float* hw = hs + (1 - p) * 1024;
            hw[0 * HID + grow] = v0;
            hw[1 * HID + grow] = v1;
            hw[2 * HID + grow] = v2;
            hw[3 * HID + grow] = v3;
            uint32_t pb = peer_hs + (uint32_t)(((1 - p) * 1024 + grow) * 4);
            asm volatile("st.shared::cluster.f32 [%0], %1;" :: "r"(pb),        "f"(v0) : "memory");
            asm volatile("st.shared::cluster.f32 [%0], %1;" :: "r"(pb + 1024), "f"(v1) : "memory");
            asm volatile("st.shared::cluster.f32 [%0], %1;" :: "r"(pb + 2048), "f"(v2) : "memory");
            asm volatile("st.shared::cluster.f32 [%0], %1;" :: "r"(pb + 3072), "f"(v3) : "memory");
            // publish h[t+1] peer half -> peer mbar[(t+1)&1]
            asm volatile("mbarrier.arrive.release.cluster.shared::cluster.b64 _, [%0];"
                         :: "r"(peer_mbar0 + (uint32_t)(((t + 1) & 1) * 8)) : "memory");
        }
        __syncthreads();                      // local half of h[t+1] visible
    }

    // Final wait (t=512): covers publish@511 (peer half of h[512] in buf 0).
    mbar_wait_cluster(mbar0, 0u);

    // Tail: hT = hs buffer 0. Rank 0: log_softmax(hT @ W_fc^T + b).
    if (rank == 0 && tid < 128) {
        const int wv = tid >> 5, l = tid & 31;        // warp = batch row
        const float* hT = hs + wv * HID;
        float t0 = 0.f, t1 = 0.f;
        #pragma unroll
        for (int j = 0; j < 8; j++) {
            int h = l + 32 * j;
            float hv = hT[h];
            t0 += hv * W_fc[h];
            t1 += hv * W_fc[HID + h];
        }
        #pragma unroll
        for (int off = 16; off > 0; off >>= 1) {
            t0 += __shfl_xor_sync(0xffffffffu, t0, off);
            t1 += __shfl_xor_sync(0xffffffffu, t1, off);
        }
        if (l == 0) {
            float l0 = t0 + b_fc[0];
            float l1 = t1 + b_fc[1];
            float m = fmaxf(l0, l1);
            float lse = m + logf(expf(l0 - m) + expf(l1 - m));
            int bg = bbase + wv;
            out[bg * 2 + 0] = l0 - lse;
            out[bg * 2 + 1] = l1 - lse;
        }
    }
    __syncthreads();
    // no remote ops can be in flight after both sides' final waits; cluster
    // barrier guarantees neither CTA tears down smem early.
    asm volatile("barrier.cluster.arrive.aligned;" ::: "memory");
    asm volatile("barrier.cluster.wait.aligned;" ::: "memory");
    if (tid == 0) {
        asm volatile("mbarrier.inval.shared.b64 [%0];" :: "r"(mbar0) : "memory");
        asm volatile("mbarrier.inval.shared.b64 [%0];" :: "r"(mbar0 + 8) : "memory");
    }
}

// ---------------------------------------------------------------------------
extern "C" void kernel_launch(void* const* d_in, const int* in_sizes, int n_in,
                              void* d_out, int out_size) {
    const float* x    = (const float*)d_in[0];
    const float* W_ih = (const float*)d_in[1];
    const float* W_hh = (const float*)d_in[2];
    const float* b_ih = (const float*)d_in[3];
    const float* b_hh = (const float*)d_in[4];
    const float* W_fc = (const float*)d_in[5];
    const float* b_fc = (const float*)d_in[6];
    float* out = (float*)d_out;

    dim3 g(T_STEPS * NBATCH / 128, HID / 128);   // (1024, 2)
    input_proj_mma<<<g, 256>>>(x, W_ih, b_ih, b_hh);

    rnn_scan_kernel<<<128, 512>>>(W_hh, W_fc, b_fc, out);
}